// round 16
// baseline (speedup 1.0000x reference)
#include <cuda_runtime.h>
#include <cuda_fp16.h>
#include <cstdint>

// ============================================================================
// myVMLSTMCell fused low-rank LSTM — R16: R14 structure (3 kernels) +
// accumulator-RAW-free MMA issue order (all hi-pass MMAs, then all lo-pass).
// ============================================================================

typedef unsigned long long ull;

#define NB 8192
#define NH 1024

__device__ uint32_t g_Af[512*20*32*4];   // A frags fp16
__device__ uint32_t g_Wh[4*128*6*32*4];  // stage2 B frags fp16 hi
__device__ uint32_t g_Wl[4*128*6*32*4];
__device__ uint32_t g_Uhi[24576*4];      // stage1 B frags fp16 hi
__device__ uint32_t g_Ulo[24576*4];
__device__ float g_cx[4*NH];
__device__ float g_ch[4*NH];
__device__ float g_cb[4*NH];

// ---- helpers ---------------------------------------------------------------
__device__ __forceinline__ float sigm_f(float v) {
    return __fdividef(1.f, 1.f + __expf(-v));
}
__device__ __forceinline__ float tanh_f(float v) {
    return 1.f - __fdividef(2.f, 1.f + __expf(2.f * v));
}
__device__ __forceinline__ void packsplit(float f0, float f1,
                                          uint32_t& hi, uint32_t& lo) {
    __half h0 = __float2half_rn(f0);
    __half h1 = __float2half_rn(f1);
    __half l0 = __float2half_rn(f0 - __half2float(h0));
    __half l1 = __float2half_rn(f1 - __half2float(h1));
    hi = (uint32_t)__half_as_ushort(h0) | ((uint32_t)__half_as_ushort(h1) << 16);
    lo = (uint32_t)__half_as_ushort(l0) | ((uint32_t)__half_as_ushort(l1) << 16);
}
__device__ __forceinline__ uint32_t packh2(float f0, float f1) {
    __half h0 = __float2half_rn(f0);
    __half h1 = __float2half_rn(f1);
    return (uint32_t)__half_as_ushort(h0) |
           ((uint32_t)__half_as_ushort(h1) << 16);
}
__device__ __forceinline__ uint32_t s2u(const void* p) {
    return (uint32_t)__cvta_generic_to_shared(p);
}
__device__ __forceinline__ void cp16(uint32_t dst, const void* src) {
    asm volatile("cp.async.cg.shared.global [%0], [%1], 16;\n"
                 :: "r"(dst), "l"(src));
}
__device__ __forceinline__ void cp_commit() {
    asm volatile("cp.async.commit_group;\n");
}
__device__ __forceinline__ void cp_wait0() {
    asm volatile("cp.async.wait_group 0;\n");
}
__device__ __forceinline__ void cp_wait1() {
    asm volatile("cp.async.wait_group 1;\n");
}
__device__ __forceinline__ void lds128(uint32_t* r, uint32_t a) {
    asm volatile("ld.shared.v4.b32 {%0,%1,%2,%3}, [%4];"
                 : "=r"(r[0]), "=r"(r[1]), "=r"(r[2]), "=r"(r[3]) : "r"(a));
}
__device__ __forceinline__ void sts32(uint32_t a, uint32_t v) {
    asm volatile("st.shared.b32 [%0], %1;" :: "r"(a), "r"(v));
}
__device__ __forceinline__ void mma_f16(float* d, const uint32_t* a,
                                        const uint32_t* b) {
    asm volatile(
        "mma.sync.aligned.m16n8k16.row.col.f32.f16.f16.f32 "
        "{%0,%1,%2,%3}, {%4,%5,%6,%7}, {%8,%9}, {%0,%1,%2,%3};\n"
        : "+f"(d[0]), "+f"(d[1]), "+f"(d[2]), "+f"(d[3])
        : "r"(a[0]), "r"(a[1]), "r"(a[2]), "r"(a[3]), "r"(b[0]), "r"(b[1]));
}

// ============================================================================
// pack_u: stage1 B frags fp16 hi/lo. 96 blocks x 256.
// ============================================================================
__global__ void pack_u_kernel(const float* __restrict__ Ux,
                              const float* __restrict__ Uh0,
                              const float* __restrict__ Uh1) {
    int idx = blockIdx.x * 256 + threadIdx.x;
    if (idx >= 24576) return;
    const float* src;
    int lane, tg, n, cc;
    if (idx < 8192) {
        int n8 = idx >> 10; cc = (idx >> 5) & 31; lane = idx & 31;
        n = n8 * 8 + (lane >> 2);
        src = Ux;
    } else {
        int rem = idx - 8192;
        int e = rem >> 12;
        int n8 = (rem >> 9) & 7; cc = (rem >> 5) & 15; lane = rem & 31;
        n = n8 * 8 + (lane >> 2);
        src = ((e & 1) ? Uh1 : Uh0) + (e >> 1) * 512 * 64;
    }
    tg = lane & 3;
    uint32_t hi[4], lo[4];
    #pragma unroll
    for (int t = 0; t < 4; t++) {
        int kp = cc * 16 + tg + t * 4;
        packsplit(src[(size_t)(2 * kp) * 64 + n],
                  src[(size_t)(2 * kp + 1) * 64 + n], hi[t], lo[t]);
    }
    *(uint4*)&g_Uhi[(size_t)idx * 4] = make_uint4(hi[0], hi[1], hi[2], hi[3]);
    *(uint4*)&g_Ulo[(size_t)idx * 4] = make_uint4(lo[0], lo[1], lo[2], lo[3]);
}

// ============================================================================
// stage1_mma: grid (64, 6).  y<5: GEMM; y==5: pack_w + coef.
//   buf (16384B): A[0,8K) W_hi[8K,12K) W_lo[12K,16K)
// ============================================================================
#define S1_DSMEM (2*16384 + 16384)

__global__ __launch_bounds__(256, 2)
void stage1_mma(const float* __restrict__ x, const float* __restrict__ h,
                const float* __restrict__ Vx, const float* __restrict__ Vh0,
                const float* __restrict__ Vh1, const float* __restrict__ Ux,
                const float* __restrict__ Uh0, const float* __restrict__ bx,
                const float* __restrict__ bh) {
    extern __shared__ char dsm[];
    uint32_t smu = s2u(dsm);

    int tid = threadIdx.x;
    int lane = tid & 31, wid = tid >> 5;
    int tg = lane & 3, lrow = lane >> 2;

    if (blockIdx.y == 5) {
        // ================== pack_w + coef ==================
        float (*V)[64] = (float(*)[64])dsm;   // 192x64 = 48KB
        int blk = blockIdx.x;
        int jblk = blk & 15, kap = blk >> 4;
        int g = kap >> 1;
        int mh0 = (((kap ^ 1) & 1) << 10) + jblk * 64;

        #pragma unroll
        for (int i = 0; i < 4; i++) {
            int idx = tid + i * 256;
            int jl = idx >> 4, kq = idx & 15;
            float4 v = *(const float4*)
                &Vx[((size_t)(kap * NH + jblk * 64 + jl)) * 64 + kq * 4];
            V[kq * 4 + 0][jl] = v.x;
            V[kq * 4 + 1][jl] = v.y;
            V[kq * 4 + 2][jl] = v.z;
            V[kq * 4 + 3][jl] = v.w;
        }
        #pragma unroll
        for (int i = 0; i < 8; i++) {
            int idx = tid + i * 256;
            int kkr = idx >> 4, jq = idx & 15;
            const float* src = (kkr < 64)
                ? &Vh0[(size_t)g * 131072 + kkr * 2048 + mh0]
                : &Vh1[(size_t)g * 131072 + (kkr - 64) * 2048 + mh0];
            *(float4*)&V[64 + kkr][jq * 4] = *(const float4*)&src[jq * 4];
        }
        __syncthreads();
        #pragma unroll
        for (int i = 0; i < 6; i++) {
            int idx = tid + i * 256;
            int n8l = idx / 192, rem = idx % 192;
            int cc = rem >> 5, ln = rem & 31;
            int jl = n8l * 8 + (ln >> 2), tgw = ln & 3;
            uint32_t hi[4], lo[4];
            #pragma unroll
            for (int t = 0; t < 4; t++) {
                int kk = 2 * (cc * 16 + tgw + t * 4);
                packsplit(V[kk][jl], V[kk + 1][jl], hi[t], lo[t]);
            }
            size_t fo = (((size_t)kap * 128 + jblk * 8 + n8l) * 6 + cc) * 32 + ln;
            *(uint4*)&g_Wh[fo * 4] = make_uint4(hi[0], hi[1], hi[2], hi[3]);
            *(uint4*)&g_Wl[fo * 4] = make_uint4(lo[0], lo[1], lo[2], lo[3]);
        }
        // ---- coef: 64 entries per block, warp-per-entry ----
        int base = blk * 64;
        #pragma unroll 1
        for (int t8 = 0; t8 < 8; t8++) {
            int idx = base + wid * 8 + t8;
            int j = idx & 1023;
            int kapc = idx >> 10;
            int gc = kapc >> 1;
            int mh = (((kapc ^ 1) & 1) << 10) + j;
            float sx = 0.f, sh = 0.f;
            #pragma unroll
            for (int rr = 0; rr < 2; rr++) {
                int r = lane + rr * 32;
                sx += Ux[j * 64 + r] * Vx[(size_t)(kapc * NH + j) * 64 + r];
                sh += Uh0[j * 64 + r]
                    * Vh0[(size_t)gc * 131072 + (size_t)r * 2048 + mh];
            }
            #pragma unroll
            for (int o = 16; o; o >>= 1) {
                sx += __shfl_xor_sync(0xFFFFFFFFu, sx, o);
                sh += __shfl_xor_sync(0xFFFFFFFFu, sh, o);
            }
            if (lane == 0) {
                g_cx[idx] = sx;
                g_ch[idx] = sh;
                g_cb[idx] = bx[(kapc << 10) + j] + bh[((kapc ^ 1) << 10) + j];
            }
        }
        return;
    }

    // ================== GEMM path ==================
    int laneT = tg * 8 + lrow;
    int wb = wid >> 1, wj = wid & 1;
    int b0 = blockIdx.x * 128;
    int cb = blockIdx.y;

    const float* Ap;
    int NC, NCC, ufrag, aoff, outoff;
    if (cb == 0) {
        Ap = x; NC = 32; NCC = 32; ufrag = 0; aoff = 0; outoff = 0;
    } else {
        int e = cb - 1;
        int g = e >> 1, i = e & 1;
        Ap = h; NC = 16; NCC = 16;
        ufrag = 8192 + e * 4096;
        aoff = ((g + i) & 1) * 512;
        outoff = 64 + g * 128 + i * 64;
    }

    float4 pf[4];
    int arow = tid >> 1, acg = tid & 1;

    #define S1_LDG(cc) do {                                                   \
        const float* src = &Ap[(size_t)(b0 + arow) * NH + aoff +              \
                               (cc) * 32 + acg * 16];                         \
        pf[0] = *(const float4*)(src);                                        \
        pf[1] = *(const float4*)(src + 4);                                    \
        pf[2] = *(const float4*)(src + 8);                                    \
        pf[3] = *(const float4*)(src + 12);                                   \
    } while (0)

    #define S1_STS(buf) do {                                                  \
        uint32_t bufb = smu + (buf) * 16384;                                  \
        const float* pff = (const float*)pf;                                  \
        uint32_t tb = bufb + (uint32_t)(((arow >> 4) * 2 + acg) * 512);       \
        uint32_t rb = (arow >> 3) & 1;                                        \
        _Pragma("unroll")                                                     \
        for (int q = 0; q < 8; q++) {                                         \
            uint32_t hv = packh2(pff[2 * q], pff[2 * q + 1]);                 \
            uint32_t ltp = (uint32_t)((q & 3) * 8 + (arow & 7));              \
            uint32_t sl  = (uint32_t)(((q >> 2) << 1) + rb);                  \
            uint32_t slp = (sl + 2 * (uint32_t)acg) & 3;                      \
            sts32(tb + ltp * 16 + slp * 4, hv);                               \
        }                                                                     \
    } while (0)

    #define S1_CPW(cc, buf) do {                                              \
        int n8 = tid >> 5, ln = tid & 31;                                     \
        uint32_t dst = smu + (buf) * 16384 + 8192 + (n8 * 32 + ln) * 16;      \
        size_t fo = (size_t)(ufrag + (n8 * NCC + (cc)) * 32 + ln) * 4;        \
        cp16(dst, &g_Uhi[fo]);                                                \
        cp16(dst + 4096, &g_Ulo[fo]);                                         \
        cp_commit();                                                          \
    } while (0)

    // two-pass MMA issue: 8 hi MMAs (independent accs), then 8 lo MMAs
    #define S1_COMPUTE(buf) do {                                              \
        uint32_t bufb = smu + (buf) * 16384;                                  \
        uint32_t bhf[4][4], blf[4][4];                                        \
        _Pragma("unroll")                                                     \
        for (int nt = 0; nt < 4; nt++) {                                      \
            uint32_t ba = bufb + 8192 + (((wj * 4 + nt) * 32) + lane) * 16;   \
            lds128(bhf[nt], ba);                                              \
            lds128(blf[nt], ba + 4096);                                       \
        }                                                                     \
        _Pragma("unroll")                                                     \
        for (int s = 0; s < 2; s++) {                                         \
            uint32_t af[2][4];                                                \
            _Pragma("unroll")                                                 \
            for (int mt = 0; mt < 2; mt++) {                                  \
                uint32_t rh[4];                                               \
                uint32_t aa = bufb +                                          \
                    ((((wb * 2 + mt) * 2 + s) * 32) + laneT) * 16;            \
                lds128(rh, aa);                                               \
                _Pragma("unroll")                                             \
                for (int i = 0; i < 4; i++)                                   \
                    af[mt][i] = rh[(i + 2 * s) & 3];                          \
            }                                                                 \
            _Pragma("unroll")                                                 \
            for (int nt = 0; nt < 4; nt++) {                                  \
                uint32_t b2h[2] = {bhf[nt][s * 2], bhf[nt][s * 2 + 1]};       \
                _Pragma("unroll")                                             \
                for (int mt = 0; mt < 2; mt++)                                \
                    mma_f16(acc[mt][nt], af[mt], b2h);                        \
            }                                                                 \
            _Pragma("unroll")                                                 \
            for (int nt = 0; nt < 4; nt++) {                                  \
                uint32_t b2l[2] = {blf[nt][s * 2], blf[nt][s * 2 + 1]};       \
                _Pragma("unroll")                                             \
                for (int mt = 0; mt < 2; mt++)                                \
                    mma_f16(acc[mt][nt], af[mt], b2l);                        \
            }                                                                 \
        }                                                                     \
    } while (0)

    float acc[2][4][4];
    #pragma unroll
    for (int a1 = 0; a1 < 2; a1++)
        #pragma unroll
        for (int a2 = 0; a2 < 4; a2++)
            #pragma unroll
            for (int a3 = 0; a3 < 4; a3++) acc[a1][a2][a3] = 0.f;

    S1_LDG(0);
    S1_CPW(0, 0);
    S1_STS(0);
    cp_wait0();
    __syncthreads();

    for (int cc = 0; cc < NC; cc++) {
        int buf = cc & 1;
        if (cc < NC - 1) {
            S1_CPW(cc + 1, buf ^ 1);
            S1_LDG(cc + 1);
        }
        S1_COMPUTE(buf);
        if (cc < NC - 1) {
            S1_STS(buf ^ 1);
            cp_wait0();
        }
        __syncthreads();
    }

    // epilogue: C-frags -> g_Af (fp16 single), 1 STG.128 per (mt,ntp)
    #pragma unroll
    for (int mt = 0; mt < 2; mt++) {
        int b16g = (b0 + wb * 32 + mt * 16) >> 4;
        #pragma unroll
        for (int ntp = 0; ntp < 2; ntp++) {
            int k16g = (outoff >> 4) + wj * 2 + ntp;
            uint4 v;
            v.x = packh2(acc[mt][2 * ntp][0],     acc[mt][2 * ntp][1]);
            v.y = packh2(acc[mt][2 * ntp][2],     acc[mt][2 * ntp][3]);
            v.z = packh2(acc[mt][2 * ntp + 1][0], acc[mt][2 * ntp + 1][1]);
            v.w = packh2(acc[mt][2 * ntp + 1][2], acc[mt][2 * ntp + 1][3]);
            size_t fo = ((size_t)b16g * 20 + k16g) * 32 + lane;
            *(uint4*)&g_Af[fo * 4] = v;
        }
    }
}

// ============================================================================
// stage2_mma: fp16 2-pass, 3-stage cp.async pipeline, fused LSTM epilogue.
//   buf (20480B): A[0,4K) W_hi[4K,12K) W_lo[12K,20K)
// ============================================================================
#define S2_DSMEM (3*20480 + 32768)

__global__ __launch_bounds__(256, 2)
void stage2_mma(const float* __restrict__ x, const float* __restrict__ h,
                const float* __restrict__ c, const float* __restrict__ dia_x,
                const float* __restrict__ dia_h, float* __restrict__ out) {
    extern __shared__ char dsm[];
    __shared__ float epi[896];
    uint32_t smu = s2u(dsm);
    float* spill = (float*)(dsm + 3 * 20480);

    int tid = threadIdx.x;
    int lane = tid & 31, wid = tid >> 5;
    int tg = lane & 3, lrow = lane >> 2;
    int wb = wid >> 2, wj = wid & 3;
    int j0 = blockIdx.x * 64;
    int b0 = blockIdx.y * 64;
    int b16base = b0 >> 4;
    int n8base = j0 >> 3;

    for (int i = tid; i < 896; i += 256) {
        float v;
        if (i < 256)       v = g_cx[(i >> 6) * 1024 + j0 + (i & 63)];
        else if (i < 512)  { int q = i - 256; v = g_ch[(q >> 6) * 1024 + j0 + (q & 63)]; }
        else if (i < 768)  { int q = i - 512; v = g_cb[(q >> 6) * 1024 + j0 + (q & 63)]; }
        else if (i < 832)  v = dia_x[j0 + i - 768];
        else               v = dia_h[j0 + i - 832];
        epi[i] = v;
    }

    #define FILL(buf, p, cc) do {                                             \
        uint32_t bufb = smu + (buf) * 20480;                                  \
        int k16base = ((cc) < 2) ? (cc) * 2 : (p) * 8 + (cc) * 2;             \
        {                                                                     \
            int b16l = tid >> 6, k16l = (tid >> 5) & 1, ln = tid & 31;        \
            size_t fo = (size_t)(((b16base + b16l) * 20 + k16base + k16l)     \
                                 * 32 + ln) * 4;                              \
            uint32_t dst = bufb + ((b16l * 2 + k16l) * 32 + ln) * 16;         \
            cp16(dst, &g_Af[fo]);                                             \
        }                                                                     \
        _Pragma("unroll")                                                     \
        for (int i2 = 0; i2 < 2; i2++) {                                      \
            int idx = tid + i2 * 256;                                         \
            int gl = idx >> 8, n8 = (idx >> 5) & 7, ln = idx & 31;            \
            size_t fo = (size_t)((((2 * (p) + gl) * 128 + n8base + n8) * 6    \
                                  + (cc)) * 32 + ln) * 4;                     \
            uint32_t dst = bufb + 4096 + ((gl * 8 + n8) * 32 + ln) * 16;      \
            cp16(dst, &g_Wh[fo]);                                             \
            cp16(dst + 8192, &g_Wl[fo]);                                      \
        }                                                                     \
        cp_commit();                                                          \
    } while (0)

    // two-pass MMA issue: 8 hi MMAs, then 8 lo MMAs (per s-step)
    #define COMPUTE(ACC, buf) do {                                            \
        uint32_t bufb = smu + (buf) * 20480;                                  \
        uint32_t bhf[2][2][4], blf[2][2][4];                                  \
        _Pragma("unroll")                                                     \
        for (int gl = 0; gl < 2; gl++)                                        \
            _Pragma("unroll")                                                 \
            for (int nt = 0; nt < 2; nt++) {                                  \
                uint32_t ba = bufb + 4096 +                                   \
                    ((gl * 8 + wj * 2 + nt) * 32 + lane) * 16;                \
                lds128(bhf[gl][nt], ba);                                      \
                lds128(blf[gl][nt], ba + 8192);                               \
            }                                                                 \
        _Pragma("unroll")                                                     \
        for (int s = 0; s < 2; s++) {                                         \
            uint32_t af[2][4];                                                \
            _Pragma("unroll")                                                 \
            for (int mt = 0; mt < 2; mt++) {                                  \
                uint32_t aa = bufb +                                          \
                    (((wb * 2 + mt) * 2 + s) * 32 + lane) * 16;               \
                lds128(af[mt], aa);                                           \
            }                                                                 \
            _Pragma("unroll")                                                 \
            for (int gl = 0; gl < 2; gl++)                                    \
                _Pragma("unroll")                                             \
                for (int nt = 0; nt < 2; nt++) {                              \
                    uint32_t b2h[2] = {bhf[gl][nt][s * 2],                    \
                                       bhf[gl][nt][s * 2 + 1]};               \
                    _Pragma("unroll")                                         \
                    for (int mt = 0; mt < 2; mt++)                            \
                        mma_f16(ACC[mt][nt][gl], af[mt], b2h);                \
                }                                                             \
            _Pragma("unroll")                                                 \
            for (int gl = 0; gl < 2; gl++)                                    \
                _Pragma("unroll")                                             \
                for (int nt = 0; nt < 2; nt++) {                              \
                    uint32_t b2l[2] = {blf[gl][nt][s * 2],                    \
                                       blf[gl][nt][s * 2 + 1]};               \
                    _Pragma("unroll")                                         \
                    for (int mt = 0; mt < 2; mt++)                            \
                        mma_f16(ACC[mt][nt][gl], af[mt], b2l);                \
                }                                                             \
        }                                                                     \
    } while (0)

    FILL(0, 0, 0);
    FILL(1, 0, 1);

    // ---------------- phase 0 (gates i,f) ----------------
    {
        float acc0[2][2][2][4];
        #pragma unroll
        for (int a1 = 0; a1 < 2; a1++)
            #pragma unroll
            for (int a2 = 0; a2 < 2; a2++)
                #pragma unroll
                for (int a3 = 0; a3 < 2; a3++)
                    #pragma unroll
                    for (int a4 = 0; a4 < 4; a4++) acc0[a1][a2][a3][a4] = 0.f;

        for (int ci = 0; ci < 6; ci++) {
            cp_wait1();
            __syncthreads();
            int nc = ci + 2;
            FILL(nc % 3, nc / 6, nc % 6);
            COMPUTE(acc0, ci % 3);
        }
        #pragma unroll
        for (int mt = 0; mt < 2; mt++)
            #pragma unroll
            for (int nt = 0; nt < 2; nt++)
                #pragma unroll
                for (int gl = 0; gl < 2; gl++)
                    #pragma unroll
                    for (int dr = 0; dr < 4; dr++) {
                        int e = ((mt * 2 + nt) * 2 + gl) * 4 + dr;
                        spill[e * 256 + tid] = acc0[mt][nt][gl][dr];
                    }
    }

    // ---------------- phase 1 (gates o,n) ----------------
    float acc1[2][2][2][4];
    #pragma unroll
    for (int a1 = 0; a1 < 2; a1++)
        #pragma unroll
        for (int a2 = 0; a2 < 2; a2++)
            #pragma unroll
            for (int a3 = 0; a3 < 2; a3++)
                #pragma unroll
                for (int a4 = 0; a4 < 4; a4++) acc1[a1][a2][a3][a4] = 0.f;

    for (int ci = 6; ci < 12; ci++) {
        if (ci < 11) cp_wait1(); else cp_wait0();
        __syncthreads();
        int nc = ci + 2;
        if (nc < 12) FILL(nc % 3, 1, nc % 6);
        COMPUTE(acc1, ci % 3);
    }

    // ---- fused LSTM epilogue ------------------------------------------------
    #pragma unroll
    for (int mt = 0; mt < 2; mt++) {
        #pragma unroll
        for (int rr = 0; rr < 2; rr++) {
            int b = b0 + wb * 32 + mt * 16 + rr * 8 + lrow;
            #pragma unroll
            for (int nt = 0; nt < 2; nt++) {
                int jj = wj * 16 + nt * 8 + 2 * tg;
                size_t off = (size_t)b * NH + j0 + jj;
                float2 xv = *(const float2*)&x[off];
                float2 hv = *(const float2*)&h[off];
                float2 cv = *(const float2*)&c[off];
                float xa[2] = {xv.x, xv.y};
                float ha[2] = {hv.x, hv.y};
                float ca[2] = {cv.x, cv.y};
                float hn[2], cn[2];
                #pragma unroll
                for (int e = 0; e < 2; e++) {
                    int jc = jj + e;
                    int dr = rr * 2 + e;
                    int eb = ((mt * 2 + nt) * 2) * 4 + dr;
                    float gi = spill[eb * 256 + tid];
                    float gf = spill[(eb + 4) * 256 + tid];
                    float go = acc1[mt][nt][0][dr];
                    float gn = acc1[mt][nt][1][dr];
                    float base = epi[768 + jc] * xa[e] + epi[832 + jc] * ha[e];
                    float v0 = gi - xa[e] * epi[jc]       - ha[e] * epi[256 + jc] + epi[512 + jc] + base;
                    float v1 = gf - xa[e] * epi[64 + jc]  - ha[e] * epi[320 + jc] + epi[576 + jc] + base;
                    float v2 = go - xa[e] * epi[128 + jc] - ha[e] * epi[384 + jc] + epi[640 + jc] + base;
                    float v3 = gn - xa[e] * epi[192 + jc] - ha[e] * epi[448 + jc] + epi[704 + jc] + base;
                    float ig = sigm_f(v0);
                    float fg = sigm_f(v1);
                    float og = sigm_f(v2);
                    float ng = tanh_f(v3);
                    float cnx = fg * ca[e] + ig * ng;
                    cn[e] = cnx;
                    hn[e] = og * tanh_f(cnx);
                }
                *(float2*)&out[off] = make_float2(hn[0], hn[1]);
                *(float2*)&out[(size_t)NB * NH + off] = make_float2(cn[0], cn[1]);
            }
        }
    }
}

// ============================================================================
extern "C" void kernel_launch(void* const* d_in, const int* in_sizes, int n_in,
                              void* d_out, int out_size) {
    const float* x     = (const float*)d_in[0];
    const float* h     = (const float*)d_in[1];
    const float* c     = (const float*)d_in[2];
    const float* dia_x = (const float*)d_in[3];
    const float* dia_h = (const float*)d_in[4];
    const float* Ux    = (const float*)d_in[5];
    const float* Vx    = (const float*)d_in[6];
    const float* Uh0   = (const float*)d_in[7];
    const float* Vh0   = (const float*)d_in[8];
    const float* Uh1   = (const float*)d_in[9];
    const float* Vh1   = (const float*)d_in[10];
    const float* bx    = (const float*)d_in[11];
    const float* bh    = (const float*)d_in[12];
    float* out = (float*)d_out;

    cudaFuncSetAttribute(stage1_mma,
                         cudaFuncAttributeMaxDynamicSharedMemorySize, S1_DSMEM);
    cudaFuncSetAttribute(stage2_mma,
                         cudaFuncAttributeMaxDynamicSharedMemorySize, S2_DSMEM);

    pack_u_kernel<<<96, 256>>>(Ux, Uh0, Uh1);
    stage1_mma<<<dim3(64, 6), 256, S1_DSMEM>>>(x, h, Vx, Vh0, Vh1, Ux, Uh0,
                                               bx, bh);
    stage2_mma<<<dim3(16, 128), 256, S2_DSMEM>>>(x, h, c, dia_x, dia_h, out);
}

// round 17
// speedup vs baseline: 1.4858x; 1.4858x over previous
#include <cuda_runtime.h>
#include <cuda_fp16.h>
#include <cstdint>

// ============================================================================
// myVMLSTMCell fused low-rank LSTM — R17: exact R14 + stage2 mt-interleaved
// MMA order only (RAW distance 1 -> 2, identical register live sets).
// ============================================================================

typedef unsigned long long ull;

#define NB 8192
#define NH 1024

__device__ uint32_t g_Af[512*20*32*4];   // A frags fp16
__device__ uint32_t g_Wh[4*128*6*32*4];  // stage2 B frags fp16 hi
__device__ uint32_t g_Wl[4*128*6*32*4];
__device__ uint32_t g_Uhi[24576*4];      // stage1 B frags fp16 hi
__device__ uint32_t g_Ulo[24576*4];
__device__ float g_cx[4*NH];
__device__ float g_ch[4*NH];
__device__ float g_cb[4*NH];

// ---- helpers ---------------------------------------------------------------
__device__ __forceinline__ float sigm_f(float v) {
    return __fdividef(1.f, 1.f + __expf(-v));
}
__device__ __forceinline__ float tanh_f(float v) {
    return 1.f - __fdividef(2.f, 1.f + __expf(2.f * v));
}
__device__ __forceinline__ void packsplit(float f0, float f1,
                                          uint32_t& hi, uint32_t& lo) {
    __half h0 = __float2half_rn(f0);
    __half h1 = __float2half_rn(f1);
    __half l0 = __float2half_rn(f0 - __half2float(h0));
    __half l1 = __float2half_rn(f1 - __half2float(h1));
    hi = (uint32_t)__half_as_ushort(h0) | ((uint32_t)__half_as_ushort(h1) << 16);
    lo = (uint32_t)__half_as_ushort(l0) | ((uint32_t)__half_as_ushort(l1) << 16);
}
__device__ __forceinline__ uint32_t packh2(float f0, float f1) {
    __half h0 = __float2half_rn(f0);
    __half h1 = __float2half_rn(f1);
    return (uint32_t)__half_as_ushort(h0) |
           ((uint32_t)__half_as_ushort(h1) << 16);
}
__device__ __forceinline__ uint32_t s2u(const void* p) {
    return (uint32_t)__cvta_generic_to_shared(p);
}
__device__ __forceinline__ void cp16(uint32_t dst, const void* src) {
    asm volatile("cp.async.cg.shared.global [%0], [%1], 16;\n"
                 :: "r"(dst), "l"(src));
}
__device__ __forceinline__ void cp_commit() {
    asm volatile("cp.async.commit_group;\n");
}
__device__ __forceinline__ void cp_wait0() {
    asm volatile("cp.async.wait_group 0;\n");
}
__device__ __forceinline__ void cp_wait1() {
    asm volatile("cp.async.wait_group 1;\n");
}
__device__ __forceinline__ void lds128(uint32_t* r, uint32_t a) {
    asm volatile("ld.shared.v4.b32 {%0,%1,%2,%3}, [%4];"
                 : "=r"(r[0]), "=r"(r[1]), "=r"(r[2]), "=r"(r[3]) : "r"(a));
}
__device__ __forceinline__ void sts32(uint32_t a, uint32_t v) {
    asm volatile("st.shared.b32 [%0], %1;" :: "r"(a), "r"(v));
}
__device__ __forceinline__ void mma_f16(float* d, const uint32_t* a,
                                        const uint32_t* b) {
    asm volatile(
        "mma.sync.aligned.m16n8k16.row.col.f32.f16.f16.f32 "
        "{%0,%1,%2,%3}, {%4,%5,%6,%7}, {%8,%9}, {%0,%1,%2,%3};\n"
        : "+f"(d[0]), "+f"(d[1]), "+f"(d[2]), "+f"(d[3])
        : "r"(a[0]), "r"(a[1]), "r"(a[2]), "r"(a[3]), "r"(b[0]), "r"(b[1]));
}

// ============================================================================
// pack_u: stage1 B frags fp16 hi/lo. 96 blocks x 256.
// ============================================================================
__global__ void pack_u_kernel(const float* __restrict__ Ux,
                              const float* __restrict__ Uh0,
                              const float* __restrict__ Uh1) {
    int idx = blockIdx.x * 256 + threadIdx.x;
    if (idx >= 24576) return;
    const float* src;
    int lane, tg, n, cc;
    if (idx < 8192) {
        int n8 = idx >> 10; cc = (idx >> 5) & 31; lane = idx & 31;
        n = n8 * 8 + (lane >> 2);
        src = Ux;
    } else {
        int rem = idx - 8192;
        int e = rem >> 12;
        int n8 = (rem >> 9) & 7; cc = (rem >> 5) & 15; lane = rem & 31;
        n = n8 * 8 + (lane >> 2);
        src = ((e & 1) ? Uh1 : Uh0) + (e >> 1) * 512 * 64;
    }
    tg = lane & 3;
    uint32_t hi[4], lo[4];
    #pragma unroll
    for (int t = 0; t < 4; t++) {
        int kp = cc * 16 + tg + t * 4;
        packsplit(src[(size_t)(2 * kp) * 64 + n],
                  src[(size_t)(2 * kp + 1) * 64 + n], hi[t], lo[t]);
    }
    *(uint4*)&g_Uhi[(size_t)idx * 4] = make_uint4(hi[0], hi[1], hi[2], hi[3]);
    *(uint4*)&g_Ulo[(size_t)idx * 4] = make_uint4(lo[0], lo[1], lo[2], lo[3]);
}

// ============================================================================
// stage1_mma: grid (64, 6).  y<5: GEMM (exact R14); y==5: pack_w + coef.
//   buf (16384B): A[0,8K) W_hi[8K,12K) W_lo[12K,16K)
// ============================================================================
#define S1_DSMEM (2*16384 + 16384)

__global__ __launch_bounds__(256, 2)
void stage1_mma(const float* __restrict__ x, const float* __restrict__ h,
                const float* __restrict__ Vx, const float* __restrict__ Vh0,
                const float* __restrict__ Vh1, const float* __restrict__ Ux,
                const float* __restrict__ Uh0, const float* __restrict__ bx,
                const float* __restrict__ bh) {
    extern __shared__ char dsm[];
    uint32_t smu = s2u(dsm);

    int tid = threadIdx.x;
    int lane = tid & 31, wid = tid >> 5;
    int tg = lane & 3, lrow = lane >> 2;

    if (blockIdx.y == 5) {
        // ================== pack_w + coef ==================
        float (*V)[64] = (float(*)[64])dsm;   // 192x64 = 48KB
        int blk = blockIdx.x;
        int jblk = blk & 15, kap = blk >> 4;
        int g = kap >> 1;
        int mh0 = (((kap ^ 1) & 1) << 10) + jblk * 64;

        #pragma unroll
        for (int i = 0; i < 4; i++) {
            int idx = tid + i * 256;
            int jl = idx >> 4, kq = idx & 15;
            float4 v = *(const float4*)
                &Vx[((size_t)(kap * NH + jblk * 64 + jl)) * 64 + kq * 4];
            V[kq * 4 + 0][jl] = v.x;
            V[kq * 4 + 1][jl] = v.y;
            V[kq * 4 + 2][jl] = v.z;
            V[kq * 4 + 3][jl] = v.w;
        }
        #pragma unroll
        for (int i = 0; i < 8; i++) {
            int idx = tid + i * 256;
            int kkr = idx >> 4, jq = idx & 15;
            const float* src = (kkr < 64)
                ? &Vh0[(size_t)g * 131072 + kkr * 2048 + mh0]
                : &Vh1[(size_t)g * 131072 + (kkr - 64) * 2048 + mh0];
            *(float4*)&V[64 + kkr][jq * 4] = *(const float4*)&src[jq * 4];
        }
        __syncthreads();
        #pragma unroll
        for (int i = 0; i < 6; i++) {
            int idx = tid + i * 256;
            int n8l = idx / 192, rem = idx % 192;
            int cc = rem >> 5, ln = rem & 31;
            int jl = n8l * 8 + (ln >> 2), tgw = ln & 3;
            uint32_t hi[4], lo[4];
            #pragma unroll
            for (int t = 0; t < 4; t++) {
                int kk = 2 * (cc * 16 + tgw + t * 4);
                packsplit(V[kk][jl], V[kk + 1][jl], hi[t], lo[t]);
            }
            size_t fo = (((size_t)kap * 128 + jblk * 8 + n8l) * 6 + cc) * 32 + ln;
            *(uint4*)&g_Wh[fo * 4] = make_uint4(hi[0], hi[1], hi[2], hi[3]);
            *(uint4*)&g_Wl[fo * 4] = make_uint4(lo[0], lo[1], lo[2], lo[3]);
        }
        // ---- coef: 64 entries per block, warp-per-entry ----
        int base = blk * 64;
        #pragma unroll 1
        for (int t8 = 0; t8 < 8; t8++) {
            int idx = base + wid * 8 + t8;
            int j = idx & 1023;
            int kapc = idx >> 10;
            int gc = kapc >> 1;
            int mh = (((kapc ^ 1) & 1) << 10) + j;
            float sx = 0.f, sh = 0.f;
            #pragma unroll
            for (int rr = 0; rr < 2; rr++) {
                int r = lane + rr * 32;
                sx += Ux[j * 64 + r] * Vx[(size_t)(kapc * NH + j) * 64 + r];
                sh += Uh0[j * 64 + r]
                    * Vh0[(size_t)gc * 131072 + (size_t)r * 2048 + mh];
            }
            #pragma unroll
            for (int o = 16; o; o >>= 1) {
                sx += __shfl_xor_sync(0xFFFFFFFFu, sx, o);
                sh += __shfl_xor_sync(0xFFFFFFFFu, sh, o);
            }
            if (lane == 0) {
                g_cx[idx] = sx;
                g_ch[idx] = sh;
                g_cb[idx] = bx[(kapc << 10) + j] + bh[((kapc ^ 1) << 10) + j];
            }
        }
        return;
    }

    // ================== GEMM path (exact R14) ==================
    int laneT = tg * 8 + lrow;
    int wb = wid >> 1, wj = wid & 1;
    int b0 = blockIdx.x * 128;
    int cb = blockIdx.y;

    const float* Ap;
    int NC, NCC, ufrag, aoff, outoff;
    if (cb == 0) {
        Ap = x; NC = 32; NCC = 32; ufrag = 0; aoff = 0; outoff = 0;
    } else {
        int e = cb - 1;
        int g = e >> 1, i = e & 1;
        Ap = h; NC = 16; NCC = 16;
        ufrag = 8192 + e * 4096;
        aoff = ((g + i) & 1) * 512;
        outoff = 64 + g * 128 + i * 64;
    }

    float4 pf[4];
    int arow = tid >> 1, acg = tid & 1;

    #define S1_LDG(cc) do {                                                   \
        const float* src = &Ap[(size_t)(b0 + arow) * NH + aoff +              \
                               (cc) * 32 + acg * 16];                         \
        pf[0] = *(const float4*)(src);                                        \
        pf[1] = *(const float4*)(src + 4);                                    \
        pf[2] = *(const float4*)(src + 8);                                    \
        pf[3] = *(const float4*)(src + 12);                                   \
    } while (0)

    #define S1_STS(buf) do {                                                  \
        uint32_t bufb = smu + (buf) * 16384;                                  \
        const float* pff = (const float*)pf;                                  \
        uint32_t tb = bufb + (uint32_t)(((arow >> 4) * 2 + acg) * 512);       \
        uint32_t rb = (arow >> 3) & 1;                                        \
        _Pragma("unroll")                                                     \
        for (int q = 0; q < 8; q++) {                                         \
            uint32_t hv = packh2(pff[2 * q], pff[2 * q + 1]);                 \
            uint32_t ltp = (uint32_t)((q & 3) * 8 + (arow & 7));              \
            uint32_t sl  = (uint32_t)(((q >> 2) << 1) + rb);                  \
            uint32_t slp = (sl + 2 * (uint32_t)acg) & 3;                      \
            sts32(tb + ltp * 16 + slp * 4, hv);                               \
        }                                                                     \
    } while (0)

    #define S1_CPW(cc, buf) do {                                              \
        int n8 = tid >> 5, ln = tid & 31;                                     \
        uint32_t dst = smu + (buf) * 16384 + 8192 + (n8 * 32 + ln) * 16;      \
        size_t fo = (size_t)(ufrag + (n8 * NCC + (cc)) * 32 + ln) * 4;        \
        cp16(dst, &g_Uhi[fo]);                                                \
        cp16(dst + 4096, &g_Ulo[fo]);                                         \
        cp_commit();                                                          \
    } while (0)

    #define S1_COMPUTE(buf) do {                                              \
        uint32_t bufb = smu + (buf) * 16384;                                  \
        uint32_t bhf[4][4], blf[4][4];                                        \
        _Pragma("unroll")                                                     \
        for (int nt = 0; nt < 4; nt++) {                                      \
            uint32_t ba = bufb + 8192 + (((wj * 4 + nt) * 32) + lane) * 16;   \
            lds128(bhf[nt], ba);                                              \
            lds128(blf[nt], ba + 4096);                                       \
        }                                                                     \
        _Pragma("unroll")                                                     \
        for (int s = 0; s < 2; s++) {                                         \
            uint32_t af[2][4];                                                \
            _Pragma("unroll")                                                 \
            for (int mt = 0; mt < 2; mt++) {                                  \
                uint32_t rh[4];                                               \
                uint32_t aa = bufb +                                          \
                    ((((wb * 2 + mt) * 2 + s) * 32) + laneT) * 16;            \
                lds128(rh, aa);                                               \
                _Pragma("unroll")                                             \
                for (int i = 0; i < 4; i++)                                   \
                    af[mt][i] = rh[(i + 2 * s) & 3];                          \
            }                                                                 \
            _Pragma("unroll")                                                 \
            for (int nt = 0; nt < 4; nt++) {                                  \
                uint32_t b2h[2] = {bhf[nt][s * 2], bhf[nt][s * 2 + 1]};       \
                uint32_t b2l[2] = {blf[nt][s * 2], blf[nt][s * 2 + 1]};       \
                _Pragma("unroll")                                             \
                for (int mt = 0; mt < 2; mt++) {                              \
                    mma_f16(acc[mt][nt], af[mt], b2h);                        \
                    mma_f16(acc[mt][nt], af[mt], b2l);                        \
                }                                                             \
            }                                                                 \
        }                                                                     \
    } while (0)

    float acc[2][4][4];
    #pragma unroll
    for (int a1 = 0; a1 < 2; a1++)
        #pragma unroll
        for (int a2 = 0; a2 < 4; a2++)
            #pragma unroll
            for (int a3 = 0; a3 < 4; a3++) acc[a1][a2][a3] = 0.f;

    S1_LDG(0);
    S1_CPW(0, 0);
    S1_STS(0);
    cp_wait0();
    __syncthreads();

    for (int cc = 0; cc < NC; cc++) {
        int buf = cc & 1;
        if (cc < NC - 1) {
            S1_CPW(cc + 1, buf ^ 1);
            S1_LDG(cc + 1);
        }
        S1_COMPUTE(buf);
        if (cc < NC - 1) {
            S1_STS(buf ^ 1);
            cp_wait0();
        }
        __syncthreads();
    }

    // epilogue: C-frags -> g_Af (fp16 single), 1 STG.128 per (mt,ntp)
    #pragma unroll
    for (int mt = 0; mt < 2; mt++) {
        int b16g = (b0 + wb * 32 + mt * 16) >> 4;
        #pragma unroll
        for (int ntp = 0; ntp < 2; ntp++) {
            int k16g = (outoff >> 4) + wj * 2 + ntp;
            uint4 v;
            v.x = packh2(acc[mt][2 * ntp][0],     acc[mt][2 * ntp][1]);
            v.y = packh2(acc[mt][2 * ntp][2],     acc[mt][2 * ntp][3]);
            v.z = packh2(acc[mt][2 * ntp + 1][0], acc[mt][2 * ntp + 1][1]);
            v.w = packh2(acc[mt][2 * ntp + 1][2], acc[mt][2 * ntp + 1][3]);
            size_t fo = ((size_t)b16g * 20 + k16g) * 32 + lane;
            *(uint4*)&g_Af[fo * 4] = v;
        }
    }
}

// ============================================================================
// stage2_mma: fp16 2-pass, 3-stage cp.async pipeline, fused LSTM epilogue.
//   buf (20480B): A[0,4K) W_hi[4K,12K) W_lo[12K,20K)
//   COMPUTE: per (gl,nt): mt0-hi, mt1-hi, mt0-lo, mt1-lo (distance-2 RAW).
// ============================================================================
#define S2_DSMEM (3*20480 + 32768)

__global__ __launch_bounds__(256, 2)
void stage2_mma(const float* __restrict__ x, const float* __restrict__ h,
                const float* __restrict__ c, const float* __restrict__ dia_x,
                const float* __restrict__ dia_h, float* __restrict__ out) {
    extern __shared__ char dsm[];
    __shared__ float epi[896];
    uint32_t smu = s2u(dsm);
    float* spill = (float*)(dsm + 3 * 20480);

    int tid = threadIdx.x;
    int lane = tid & 31, wid = tid >> 5;
    int tg = lane & 3, lrow = lane >> 2;
    int wb = wid >> 2, wj = wid & 3;
    int j0 = blockIdx.x * 64;
    int b0 = blockIdx.y * 64;
    int b16base = b0 >> 4;
    int n8base = j0 >> 3;

    for (int i = tid; i < 896; i += 256) {
        float v;
        if (i < 256)       v = g_cx[(i >> 6) * 1024 + j0 + (i & 63)];
        else if (i < 512)  { int q = i - 256; v = g_ch[(q >> 6) * 1024 + j0 + (q & 63)]; }
        else if (i < 768)  { int q = i - 512; v = g_cb[(q >> 6) * 1024 + j0 + (q & 63)]; }
        else if (i < 832)  v = dia_x[j0 + i - 768];
        else               v = dia_h[j0 + i - 832];
        epi[i] = v;
    }

    #define FILL(buf, p, cc) do {                                             \
        uint32_t bufb = smu + (buf) * 20480;                                  \
        int k16base = ((cc) < 2) ? (cc) * 2 : (p) * 8 + (cc) * 2;             \
        {                                                                     \
            int b16l = tid >> 6, k16l = (tid >> 5) & 1, ln = tid & 31;        \
            size_t fo = (size_t)(((b16base + b16l) * 20 + k16base + k16l)     \
                                 * 32 + ln) * 4;                              \
            uint32_t dst = bufb + ((b16l * 2 + k16l) * 32 + ln) * 16;         \
            cp16(dst, &g_Af[fo]);                                             \
        }                                                                     \
        _Pragma("unroll")                                                     \
        for (int i2 = 0; i2 < 2; i2++) {                                      \
            int idx = tid + i2 * 256;                                         \
            int gl = idx >> 8, n8 = (idx >> 5) & 7, ln = idx & 31;            \
            size_t fo = (size_t)((((2 * (p) + gl) * 128 + n8base + n8) * 6    \
                                  + (cc)) * 32 + ln) * 4;                     \
            uint32_t dst = bufb + 4096 + ((gl * 8 + n8) * 32 + ln) * 16;      \
            cp16(dst, &g_Wh[fo]);                                             \
            cp16(dst + 8192, &g_Wl[fo]);                                      \
        }                                                                     \
        cp_commit();                                                          \
    } while (0)

    #define COMPUTE(ACC, buf) do {                                            \
        uint32_t bufb = smu + (buf) * 20480;                                  \
        uint32_t bhf[2][2][4], blf[2][2][4];                                  \
        _Pragma("unroll")                                                     \
        for (int gl = 0; gl < 2; gl++)                                        \
            _Pragma("unroll")                                                 \
            for (int nt = 0; nt < 2; nt++) {                                  \
                uint32_t ba = bufb + 4096 +                                   \
                    ((gl * 8 + wj * 2 + nt) * 32 + lane) * 16;                \
                lds128(bhf[gl][nt], ba);                                      \
                lds128(blf[gl][nt], ba + 8192);                               \
            }                                                                 \
        _Pragma("unroll")                                                     \
        for (int s = 0; s < 2; s++) {                                         \
            uint32_t af[2][4];                                                \
            _Pragma("unroll")                                                 \
            for (int mt = 0; mt < 2; mt++) {                                  \
                uint32_t aa = bufb +                                          \
                    (((wb * 2 + mt) * 2 + s) * 32 + lane) * 16;               \
                lds128(af[mt], aa);                                           \
            }                                                                 \
            _Pragma("unroll")                                                 \
            for (int gl = 0; gl < 2; gl++)                                    \
                _Pragma("unroll")                                             \
                for (int nt = 0; nt < 2; nt++) {                              \
                    uint32_t b2h[2] = {bhf[gl][nt][s * 2], bhf[gl][nt][s * 2 + 1]}; \
                    uint32_t b2l[2] = {blf[gl][nt][s * 2], blf[gl][nt][s * 2 + 1]}; \
                    mma_f16(ACC[0][nt][gl], af[0], b2h);                      \
                    mma_f16(ACC[1][nt][gl], af[1], b2h);                      \
                    mma_f16(ACC[0][nt][gl], af[0], b2l);                      \
                    mma_f16(ACC[1][nt][gl], af[1], b2l);                      \
                }                                                             \
        }                                                                     \
    } while (0)

    FILL(0, 0, 0);
    FILL(1, 0, 1);

    // ---------------- phase 0 (gates i,f) ----------------
    {
        float acc0[2][2][2][4];
        #pragma unroll
        for (int a1 = 0; a1 < 2; a1++)
            #pragma unroll
            for (int a2 = 0; a2 < 2; a2++)
                #pragma unroll
                for (int a3 = 0; a3 < 2; a3++)
                    #pragma unroll
                    for (int a4 = 0; a4 < 4; a4++) acc0[a1][a2][a3][a4] = 0.f;

        for (int ci = 0; ci < 6; ci++) {
            cp_wait1();
            __syncthreads();
            int nc = ci + 2;
            FILL(nc % 3, nc / 6, nc % 6);
            COMPUTE(acc0, ci % 3);
        }
        #pragma unroll
        for (int mt = 0; mt < 2; mt++)
            #pragma unroll
            for (int nt = 0; nt < 2; nt++)
                #pragma unroll
                for (int gl = 0; gl < 2; gl++)
                    #pragma unroll
                    for (int dr = 0; dr < 4; dr++) {
                        int e = ((mt * 2 + nt) * 2 + gl) * 4 + dr;
                        spill[e * 256 + tid] = acc0[mt][nt][gl][dr];
                    }
    }

    // ---------------- phase 1 (gates o,n) ----------------
    float acc1[2][2][2][4];
    #pragma unroll
    for (int a1 = 0; a1 < 2; a1++)
        #pragma unroll
        for (int a2 = 0; a2 < 2; a2++)
            #pragma unroll
            for (int a3 = 0; a3 < 2; a3++)
                #pragma unroll
                for (int a4 = 0; a4 < 4; a4++) acc1[a1][a2][a3][a4] = 0.f;

    for (int ci = 6; ci < 12; ci++) {
        if (ci < 11) cp_wait1(); else cp_wait0();
        __syncthreads();
        int nc = ci + 2;
        if (nc < 12) FILL(nc % 3, 1, nc % 6);
        COMPUTE(acc1, ci % 3);
    }

    // ---- fused LSTM epilogue ------------------------------------------------
    #pragma unroll
    for (int mt = 0; mt < 2; mt++) {
        #pragma unroll
        for (int rr = 0; rr < 2; rr++) {
            int b = b0 + wb * 32 + mt * 16 + rr * 8 + lrow;
            #pragma unroll
            for (int nt = 0; nt < 2; nt++) {
                int jj = wj * 16 + nt * 8 + 2 * tg;
                size_t off = (size_t)b * NH + j0 + jj;
                float2 xv = *(const float2*)&x[off];
                float2 hv = *(const float2*)&h[off];
                float2 cv = *(const float2*)&c[off];
                float xa[2] = {xv.x, xv.y};
                float ha[2] = {hv.x, hv.y};
                float ca[2] = {cv.x, cv.y};
                float hn[2], cn[2];
                #pragma unroll
                for (int e = 0; e < 2; e++) {
                    int jc = jj + e;
                    int dr = rr * 2 + e;
                    int eb = ((mt * 2 + nt) * 2) * 4 + dr;
                    float gi = spill[eb * 256 + tid];
                    float gf = spill[(eb + 4) * 256 + tid];
                    float go = acc1[mt][nt][0][dr];
                    float gn = acc1[mt][nt][1][dr];
                    float base = epi[768 + jc] * xa[e] + epi[832 + jc] * ha[e];
                    float v0 = gi - xa[e] * epi[jc]       - ha[e] * epi[256 + jc] + epi[512 + jc] + base;
                    float v1 = gf - xa[e] * epi[64 + jc]  - ha[e] * epi[320 + jc] + epi[576 + jc] + base;
                    float v2 = go - xa[e] * epi[128 + jc] - ha[e] * epi[384 + jc] + epi[640 + jc] + base;
                    float v3 = gn - xa[e] * epi[192 + jc] - ha[e] * epi[448 + jc] + epi[704 + jc] + base;
                    float ig = sigm_f(v0);
                    float fg = sigm_f(v1);
                    float og = sigm_f(v2);
                    float ng = tanh_f(v3);
                    float cnx = fg * ca[e] + ig * ng;
                    cn[e] = cnx;
                    hn[e] = og * tanh_f(cnx);
                }
                *(float2*)&out[off] = make_float2(hn[0], hn[1]);
                *(float2*)&out[(size_t)NB * NH + off] = make_float2(cn[0], cn[1]);
            }
        }
    }
}

// ============================================================================
extern "C" void kernel_launch(void* const* d_in, const int* in_sizes, int n_in,
                              void* d_out, int out_size) {
    const float* x     = (const float*)d_in[0];
    const float* h     = (const float*)d_in[1];
    const float* c     = (const float*)d_in[2];
    const float* dia_x = (const float*)d_in[3];
    const float* dia_h = (const float*)d_in[4];
    const float* Ux    = (const float*)d_in[5];
    const float* Vx    = (const float*)d_in[6];
    const float* Uh0   = (const float*)d_in[7];
    const float* Vh0   = (const float*)d_in[8];
    const float* Uh1   = (const float*)d_in[9];
    const float* Vh1   = (const float*)d_in[10];
    const float* bx    = (const float*)d_in[11];
    const float* bh    = (const float*)d_in[12];
    float* out = (float*)d_out;

    cudaFuncSetAttribute(stage1_mma,
                         cudaFuncAttributeMaxDynamicSharedMemorySize, S1_DSMEM);
    cudaFuncSetAttribute(stage2_mma,
                         cudaFuncAttributeMaxDynamicSharedMemorySize, S2_DSMEM);

    pack_u_kernel<<<96, 256>>>(Ux, Uh0, Uh1);
    stage1_mma<<<dim3(64, 6), 256, S1_DSMEM>>>(x, h, Vx, Vh0, Vh1, Ux, Uh0,
                                               bx, bh);
    stage2_mma<<<dim3(16, 128), 256, S2_DSMEM>>>(x, h, c, dia_x, dia_h, out);
}